// round 9
// baseline (speedup 1.0000x reference)
#include <cuda_runtime.h>
#include <cuda_bf16.h>
#include <math.h>
#include <stdint.h>

// Problem constants
#define B_SZ 8
#define T_SZ 2048
#define C_SZ 1024
#define H_SZ 64
#define WIN 64
#define NGLOB 64
#define NRAND 64

#define BT (B_SZ * T_SZ)          // 16384 rows

// Scratch for projected q, k, v  (4 MB each) — device globals, no allocation.
__device__ float g_Q[BT * H_SZ];
__device__ float g_K[BT * H_SZ];
__device__ float g_V[BT * H_SZ];

__device__ __forceinline__ void mma_bf16(float* c, const uint32_t* a, const uint32_t* b) {
    asm volatile(
        "mma.sync.aligned.m16n8k16.row.col.f32.bf16.bf16.f32 "
        "{%0,%1,%2,%3}, {%4,%5,%6,%7}, {%8,%9}, {%0,%1,%2,%3};"
        : "+f"(c[0]), "+f"(c[1]), "+f"(c[2]), "+f"(c[3])
        : "r"(a[0]), "r"(a[1]), "r"(a[2]), "r"(a[3]),
          "r"(b[0]), "r"(b[1]));
}

// ---------------------------------------------------------------------------
// FUSED projection GEMM (Q,K,V), bf16 3-split, ping-pong smem (UNCHANGED).
// ---------------------------------------------------------------------------
#define KC 16
#define PADK 12
#define NCHUNK (C_SZ / KC)        // 64

__global__ __launch_bounds__(256, 2) void proj_tc_kernel(
    const float* __restrict__ x,
    const float* __restrict__ Wq,
    const float* __restrict__ Wk,
    const float* __restrict__ Wv)
{
    __shared__ __align__(16) uint32_t sm_h[2][256][PADK];
    __shared__ __align__(16) uint32_t sm_l[2][256][PADK];

    const int m0   = blockIdx.x * 64;
    const int tid  = threadIdx.x;
    const int warp = tid >> 5;
    const int lane = tid & 31;
    const int grp  = lane >> 2;   // 0..7
    const int tig  = lane & 3;    // 0..3
    const int mh   = warp & 1;    // M half (32 rows)
    const int nq   = warp >> 1;   // N quarter (6 n-tiles)

    const float* srcs[8];
    int rp[8];
#pragma unroll
    for (int it = 0; it < 8; it++) {
        const int i = it * 256 + tid;
        int r, w;
        const float* base;
        if (it < 2) {
            r = i >> 3; w = i & 7;
            base = &x[(size_t)(m0 + r) * C_SZ];
            rp[it] = r * PADK;
        } else {
            const int j = i - 512;
            r = j >> 3; w = j & 7;
            base = (r < 64)  ? &Wq[(size_t)r * C_SZ]
                 : (r < 128) ? &Wk[(size_t)(r - 64) * C_SZ]
                             : &Wv[(size_t)(r - 128) * C_SZ];
            rp[it] = (64 + r) * PADK;
        }
        srcs[it] = base + w * 2;
        rp[it] += 2 * (w & 3) + (w >> 2);
    }

    float acc[2][6][4];
#pragma unroll
    for (int mt = 0; mt < 2; mt++)
#pragma unroll
        for (int i = 0; i < 6; i++)
#pragma unroll
            for (int j = 0; j < 4; j++) acc[mt][i][j] = 0.f;

    float2 pf[8];
#pragma unroll
    for (int it = 0; it < 8; it++) pf[it] = *(const float2*)srcs[it];
#pragma unroll
    for (int it = 0; it < 8; it++) {
        const float a = pf[it].x, b = pf[it].y;
        __nv_bfloat162 h2 = __floats2bfloat162_rn(a, b);
        const uint32_t hu = *(const uint32_t*)&h2;
        const float ha = __uint_as_float(hu << 16);
        const float hb = __uint_as_float(hu & 0xFFFF0000u);
        __nv_bfloat162 l2 = __floats2bfloat162_rn(a - ha, b - hb);
        ((uint32_t*)sm_h[0])[rp[it]] = hu;
        ((uint32_t*)sm_l[0])[rp[it]] = *(const uint32_t*)&l2;
    }

    for (int c = 0; c < NCHUNK; c++) {
        __syncthreads();
        const int cur = c & 1;
        const bool more = (c + 1 < NCHUNK);

        if (more) {
            const int koff = (c + 1) * KC;
#pragma unroll
            for (int it = 0; it < 8; it++)
                pf[it] = *(const float2*)(srcs[it] + koff);
        }

        uint32_t ah[2][4], al[2][4];
#pragma unroll
        for (int mt = 0; mt < 2; mt++) {
            const int mrow = mh * 32 + mt * 16 + grp;
            uint2 q0 = *(const uint2*)&sm_h[cur][mrow][tig * 2];
            uint2 q1 = *(const uint2*)&sm_h[cur][mrow + 8][tig * 2];
            ah[mt][0] = q0.x; ah[mt][2] = q0.y;
            ah[mt][1] = q1.x; ah[mt][3] = q1.y;
            uint2 s0 = *(const uint2*)&sm_l[cur][mrow][tig * 2];
            uint2 s1 = *(const uint2*)&sm_l[cur][mrow + 8][tig * 2];
            al[mt][0] = s0.x; al[mt][2] = s0.y;
            al[mt][1] = s1.x; al[mt][3] = s1.y;
        }

#pragma unroll
        for (int i = 0; i < 6; i++) {
            const int wrow = 64 + (nq * 6 + i) * 8 + grp;
            uint2 bh2 = *(const uint2*)&sm_h[cur][wrow][tig * 2];
            uint2 bl2 = *(const uint2*)&sm_l[cur][wrow][tig * 2];
            uint32_t bh[2] = {bh2.x, bh2.y};
            uint32_t bl[2] = {bl2.x, bl2.y};
#pragma unroll
            for (int mt = 0; mt < 2; mt++) {
                mma_bf16(acc[mt][i], al[mt], bh);
                mma_bf16(acc[mt][i], ah[mt], bl);
                mma_bf16(acc[mt][i], ah[mt], bh);
            }
        }

        if (more) {
            const int nxt = cur ^ 1;
#pragma unroll
            for (int it = 0; it < 8; it++) {
                const float a = pf[it].x, b = pf[it].y;
                __nv_bfloat162 h2 = __floats2bfloat162_rn(a, b);
                const uint32_t hu = *(const uint32_t*)&h2;
                const float ha = __uint_as_float(hu << 16);
                const float hb = __uint_as_float(hu & 0xFFFF0000u);
                __nv_bfloat162 l2 = __floats2bfloat162_rn(a - ha, b - hb);
                ((uint32_t*)sm_h[nxt])[rp[it]] = hu;
                ((uint32_t*)sm_l[nxt])[rp[it]] = *(const uint32_t*)&l2;
            }
        }
    }

#pragma unroll
    for (int mt = 0; mt < 2; mt++) {
        const int mwr = m0 + mh * 32 + mt * 16 + grp;
#pragma unroll
        for (int i = 0; i < 6; i++) {
            const int ntg = nq * 6 + i;
            float* out = (ntg < 8) ? g_Q : (ntg < 16) ? g_K : g_V;
            const int col = (ntg & 7) * 8 + tig * 2;
            *(float2*)&out[(size_t)mwr * H_SZ + col] =
                make_float2(acc[mt][i][0], acc[mt][i][1]);
            *(float2*)&out[(size_t)(mwr + 8) * H_SZ + col] =
                make_float2(acc[mt][i][2], acc[mt][i][3]);
        }
    }
}

// ---------------------------------------------------------------------------
// Sparse BigBird attention, 4 query rows per block, SOFTWARE-PIPELINED:
// score loop prefetches next iteration's K tile (clamped index, warp-uniform
// guard keeps shuffles convergent); V loop prefetches next (weights, V) pair.
// ---------------------------------------------------------------------------
#define QR 4
#define MAXC 392

__global__ __launch_bounds__(256, 4) void attn4_kernel(
    const int* __restrict__ random_cols,
    float* __restrict__ out)
{
    const int blk = blockIdx.x;            // 0 .. 4095
    const int b   = blk >> 9;              // 512 blocks per batch
    const int r0  = (blk & 511) * QR;
    const int r3  = r0 + 3;

    __shared__ int   cols[MAXC];
    __shared__ __align__(16) float sc[MAXC][4];
    __shared__ __align__(16) float qs[QR][H_SZ];
    __shared__ uint32_t rbit[QR][64];
    __shared__ uint32_t ubit[64];
    __shared__ int   s_n;
    __shared__ __align__(16) float4 red4[8];
    __shared__ float4 s_mx4, s_inv4;
    __shared__ __align__(16) float outp[16][256];   // [group][row*64+dim]

    const int tid  = threadIdx.x;
    const int lane = tid & 31;
    const int warp = tid >> 5;
    const int i4   = tid >> 6;    // 0..3  (row for setup)
    const int j4   = tid & 63;    // 0..63

    // ---- phase 0: init + loads ----
    rbit[i4][j4] = 0;
    if (tid < 64) ubit[tid] = 0;
    if (tid == 0) s_n = 0;
    const int myrnd = random_cols[(r0 + i4) * NRAND + j4];
    qs[i4][j4] = g_Q[((size_t)b * T_SZ + r0 + i4) * H_SZ + j4];

    const int lo0 = max(0, r0 - (WIN - 1));
    const int gn  = min(NGLOB, r3 + 1);
    const int l0u = max(64, lo0);
    const int ln  = max(0, r3 - l0u + 1);
    __syncthreads();

    // ---- phase 1: bitmaps + union list ----
    atomicOr(&rbit[i4][myrnd >> 5], 1u << (myrnd & 31));
    if (tid < gn) cols[tid] = tid;
    if (tid >= 64 && tid < 64 + ln) cols[gn + tid - 64] = l0u + (tid - 64);
    if (myrnd >= 64 && myrnd < lo0) {
        uint32_t bit = 1u << (myrnd & 31);
        uint32_t old = atomicOr(&ubit[myrnd >> 5], bit);
        if (!(old & bit)) {
            int p = atomicAdd(&s_n, 1);
            cols[gn + ln + p] = myrnd;
        }
    }
    __syncthreads();
    const int n = gn + ln + s_n;

    // ---- score pass: 8-lane groups, prefetch-pipelined ----
    const int l8 = lane & 7;
    const int g8 = lane >> 3;
    float4 qA[QR], qB[QR];
#pragma unroll
    for (int i = 0; i < QR; i++) {
        qA[i] = *(const float4*)&qs[i][l8 * 8];
        qB[i] = *(const float4*)&qs[i][l8 * 8 + 4];
    }
    const size_t bbase = (size_t)b * T_SZ;

    // prefetch iteration 0
    float4 ka, kb;
    {
        const int cc = cols[min(warp * 4 + g8, n - 1)];
        const float* kp = &g_K[(bbase + cc) * H_SZ + l8 * 8];
        ka = *(const float4*)kp;
        kb = *(const float4*)(kp + 4);
    }

    for (int ci0 = warp * 4; ci0 < n; ci0 += 32) {     // warp-uniform bound
        const int  ci  = ci0 + g8;
        const bool act = (ci < n);
        const float4 kA = ka, kB = kb;

        // prefetch next iteration's K (warp-uniform guard, clamped index)
        if (ci0 + 32 < n) {
            const int cc = cols[min(ci0 + 32 + g8, n - 1)];
            const float* kp = &g_K[(bbase + cc) * H_SZ + l8 * 8];
            ka = *(const float4*)kp;
            kb = *(const float4*)(kp + 4);
        }

        float p0 = qA[0].x*kA.x + qA[0].y*kA.y + qA[0].z*kA.z + qA[0].w*kA.w
                 + qB[0].x*kB.x + qB[0].y*kB.y + qB[0].z*kB.z + qB[0].w*kB.w;
        float p1 = qA[1].x*kA.x + qA[1].y*kA.y + qA[1].z*kA.z + qA[1].w*kA.w
                 + qB[1].x*kB.x + qB[1].y*kB.y + qB[1].z*kB.z + qB[1].w*kB.w;
        float p2 = qA[2].x*kA.x + qA[2].y*kA.y + qA[2].z*kA.z + qA[2].w*kA.w
                 + qB[2].x*kB.x + qB[2].y*kB.y + qB[2].z*kB.z + qB[2].w*kB.w;
        float p3 = qA[3].x*kA.x + qA[3].y*kA.y + qA[3].z*kA.z + qA[3].w*kA.w
                 + qB[3].x*kB.x + qB[3].y*kB.y + qB[3].z*kB.z + qB[3].w*kB.w;
#pragma unroll
        for (int o = 4; o; o >>= 1) {
            p0 += __shfl_xor_sync(0xffffffffu, p0, o);
            p1 += __shfl_xor_sync(0xffffffffu, p1, o);
            p2 += __shfl_xor_sync(0xffffffffu, p2, o);
            p3 += __shfl_xor_sync(0xffffffffu, p3, o);
        }
        if (act && l8 < QR) {
            const int ri = r0 + l8;
            const int c  = cols[ci];
            float pv = (l8 == 0) ? p0 : (l8 == 1) ? p1 : (l8 == 2) ? p2 : p3;
            bool allowed = (c <= ri) &&
                           ((c > ri - WIN) || (c < NGLOB) ||
                            ((rbit[l8][c >> 5] >> (c & 31)) & 1u));
            sc[ci][l8] = allowed ? pv * 0.125f : -INFINITY;
        }
    }
    __syncthreads();

    // ---- softmax pass 1: componentwise max over 4 rows ----
    float4 m4 = make_float4(-1e30f, -1e30f, -1e30f, -1e30f);
    for (int ci = tid; ci < n; ci += 256) {
        float4 s4 = *(const float4*)&sc[ci][0];
        m4.x = fmaxf(m4.x, s4.x); m4.y = fmaxf(m4.y, s4.y);
        m4.z = fmaxf(m4.z, s4.z); m4.w = fmaxf(m4.w, s4.w);
    }
#pragma unroll
    for (int o = 16; o; o >>= 1) {
        m4.x = fmaxf(m4.x, __shfl_xor_sync(0xffffffffu, m4.x, o));
        m4.y = fmaxf(m4.y, __shfl_xor_sync(0xffffffffu, m4.y, o));
        m4.z = fmaxf(m4.z, __shfl_xor_sync(0xffffffffu, m4.z, o));
        m4.w = fmaxf(m4.w, __shfl_xor_sync(0xffffffffu, m4.w, o));
    }
    if (lane == 0) red4[warp] = m4;
    __syncthreads();
    if (tid == 0) {
        float4 m = red4[0];
#pragma unroll
        for (int w = 1; w < 8; w++) {
            m.x = fmaxf(m.x, red4[w].x); m.y = fmaxf(m.y, red4[w].y);
            m.z = fmaxf(m.z, red4[w].z); m.w = fmaxf(m.w, red4[w].w);
        }
        s_mx4 = m;
    }
    __syncthreads();
    const float4 mx = s_mx4;

    // ---- softmax pass 2: exp + sum ----
    float4 sum4 = make_float4(0.f, 0.f, 0.f, 0.f);
    for (int ci = tid; ci < n; ci += 256) {
        float4 s4 = *(const float4*)&sc[ci][0];
        s4.x = __expf(s4.x - mx.x); s4.y = __expf(s4.y - mx.y);
        s4.z = __expf(s4.z - mx.z); s4.w = __expf(s4.w - mx.w);
        *(float4*)&sc[ci][0] = s4;
        sum4.x += s4.x; sum4.y += s4.y; sum4.z += s4.z; sum4.w += s4.w;
    }
#pragma unroll
    for (int o = 16; o; o >>= 1) {
        sum4.x += __shfl_xor_sync(0xffffffffu, sum4.x, o);
        sum4.y += __shfl_xor_sync(0xffffffffu, sum4.y, o);
        sum4.z += __shfl_xor_sync(0xffffffffu, sum4.z, o);
        sum4.w += __shfl_xor_sync(0xffffffffu, sum4.w, o);
    }
    if (lane == 0) red4[warp] = sum4;
    __syncthreads();
    if (tid == 0) {
        float4 s = red4[0];
#pragma unroll
        for (int w = 1; w < 8; w++) {
            s.x += red4[w].x; s.y += red4[w].y;
            s.z += red4[w].z; s.w += red4[w].w;
        }
        s_inv4 = make_float4(1.f/s.x, 1.f/s.y, 1.f/s.z, 1.f/s.w);
    }
    __syncthreads();

    // ---- V pass: 16 groups of 16 threads, prefetch-pipelined ----
    const int dg = tid & 15;
    const int gq = tid >> 4;
    float4 a0 = make_float4(0,0,0,0), a1 = a0, a2 = a0, a3 = a0;

    float4 wn, vn;
    if (gq < n) {
        wn = *(const float4*)&sc[gq][0];
        vn = *(const float4*)&g_V[(bbase + cols[gq]) * H_SZ + dg * 4];
    }
    for (int ci = gq; ci < n; ci += 16) {
        const float4 w4 = wn, v = vn;
        if (ci + 16 < n) {
            wn = *(const float4*)&sc[ci + 16][0];
            vn = *(const float4*)&g_V[(bbase + cols[ci + 16]) * H_SZ + dg * 4];
        }
        a0.x += w4.x*v.x; a0.y += w4.x*v.y; a0.z += w4.x*v.z; a0.w += w4.x*v.w;
        a1.x += w4.y*v.x; a1.y += w4.y*v.y; a1.z += w4.y*v.z; a1.w += w4.y*v.w;
        a2.x += w4.z*v.x; a2.y += w4.z*v.y; a2.z += w4.z*v.z; a2.w += w4.z*v.w;
        a3.x += w4.w*v.x; a3.y += w4.w*v.y; a3.z += w4.w*v.z; a3.w += w4.w*v.w;
    }
    *(float4*)&outp[gq][0 * 64 + dg * 4] = a0;
    *(float4*)&outp[gq][1 * 64 + dg * 4] = a1;
    *(float4*)&outp[gq][2 * 64 + dg * 4] = a2;
    *(float4*)&outp[gq][3 * 64 + dg * 4] = a3;
    __syncthreads();

    // ---- final reduce + normalize ----
    {
        const int i = tid >> 6;
        const int d = tid & 63;
        float o = 0.f;
#pragma unroll
        for (int g2 = 0; g2 < 16; g2++) o += outp[g2][i * 64 + d];
        float inv = (i == 0) ? s_inv4.x : (i == 1) ? s_inv4.y
                  : (i == 2) ? s_inv4.z : s_inv4.w;
        out[((size_t)b * T_SZ + r0 + i) * H_SZ + d] = o * inv;
    }
}

// ---------------------------------------------------------------------------
// kernel_launch — inputs per metadata order: x, random_cols, Wk, Wq, Wv
// ---------------------------------------------------------------------------
extern "C" void kernel_launch(void* const* d_in, const int* in_sizes, int n_in,
                              void* d_out, int out_size)
{
    const float* x           = (const float*)d_in[0];
    const int*   random_cols = (const int*)  d_in[1];
    const float* Wk          = (const float*)d_in[2];
    const float* Wq          = (const float*)d_in[3];
    const float* Wv          = (const float*)d_in[4];
    float* out = (float*)d_out;

    proj_tc_kernel<<<BT / 64, 256>>>(x, Wq, Wk, Wv);

    attn4_kernel<<<BT / QR, 256>>>(random_cols, out);
}